// round 14
// baseline (speedup 1.0000x reference)
#include <cuda_runtime.h>

#define Bsz 4096
#define Lsz 512
#define Msz 17
#define Hsz 17
#define Tch 4
#define NCHUNK (Lsz / Tch)          // 128
#define PAIR_B 14                   // thread-rows per block; each thread owns 2 rows
#define ROWS_B (2 * PAIR_B)         // 28 rows per block
#define NTHREADS (PAIR_B * Hsz)     // 238 -> 2 blocks/SM
#define NBLOCKS ((Bsz + ROWS_B - 1) / ROWS_B)  // 147
#define ROW_STRIDE (Lsz * Msz)      // floats between consecutive rows of x / xout
#define OROW_STRIDE (Lsz * Hsz)

typedef unsigned long long u64;

__device__ __forceinline__ u64 pk2(float a, float b) {
    u64 r; asm("mov.b64 %0, {%1, %2};" : "=l"(r) : "f"(a), "f"(b)); return r;
}
__device__ __forceinline__ void upk2(u64 v, float &a, float &b) {
    asm("mov.b64 {%0, %1}, %2;" : "=f"(a), "=f"(b) : "l"(v));
}
__device__ __forceinline__ void ffma2(u64 &d, u64 a, u64 b) {
    asm("fma.rn.f32x2 %0, %1, %2, %0;" : "+l"(d) : "l"(a), "l"(b));
}
__device__ __forceinline__ float tanh_ap(float z) {
    float r; asm("tanh.approx.f32 %0, %1;" : "=f"(r) : "f"(z)); return r;
}

__global__ __launch_bounds__(NTHREADS, 2) void lstm_fused_kernel(
    const float* __restrict__ x,
    const float* __restrict__ Wih,
    const float* __restrict__ Whh,
    const float* __restrict__ bih,
    const float* __restrict__ bhh,
    float* __restrict__ out)
{
    __shared__ __align__(16) ulonglong2 wih_s[Msz * Hsz];   // {if,go} pairs
    __shared__ __align__(16) float sx[ROWS_B][Tch * Msz];   // x chunks, plain, [k*4+t]
    __shared__ __align__(16) float shp[2][ROWS_B][20];      // h states, plain, dbl-buf

    const int tid = threadIdx.x;
    const int j = tid % Hsz;
    const int y = tid / Hsz;            // 0..13 ; rows y and y+14
    const int r0 = blockIdx.x * ROWS_B + y;
    const int r1 = r0 + PAIR_B;
    const bool act0 = (r0 < Bsz);
    const bool act1 = (r1 < Bsz);
    const int bb0 = act0 ? r0 : (Bsz - 1);
    const int bb1 = act1 ? r1 : (Bsz - 1);

    // ---- W_ih into smem; sigmoid gates (i,f,o) pre-scaled by 0.5 ----
    for (int idx = tid; idx < Msz * Hsz; idx += NTHREADS) {
        int k = idx / Hsz, jj = idx % Hsz;
        ulonglong2 w2;
        w2.x = pk2(0.5f * Wih[jj * Msz + k],
                   0.5f * Wih[(Hsz + jj) * Msz + k]);
        w2.y = pk2(Wih[(2 * Hsz + jj) * Msz + k],
                   0.5f * Wih[(3 * Hsz + jj) * Msz + k]);
        wih_s[idx] = w2;
    }

    // ---- W_hh in registers (shared by both rows): 8 pairs/gate + scalar k16 ----
    u64 wh0[8], wh1[8], wh2[8], wh3[8];
    float w16_0, w16_1, w16_2, w16_3;
    {
        const float* w0 = Whh + (0 * Hsz + j) * Hsz;
        const float* w1 = Whh + (1 * Hsz + j) * Hsz;
        const float* w2 = Whh + (2 * Hsz + j) * Hsz;
        const float* w3 = Whh + (3 * Hsz + j) * Hsz;
#pragma unroll
        for (int p = 0; p < 8; p++) {
            wh0[p] = pk2(0.5f * w0[2 * p], 0.5f * w0[2 * p + 1]);
            wh1[p] = pk2(0.5f * w1[2 * p], 0.5f * w1[2 * p + 1]);
            wh2[p] = pk2(w2[2 * p],        w2[2 * p + 1]);
            wh3[p] = pk2(0.5f * w3[2 * p], 0.5f * w3[2 * p + 1]);
        }
        w16_0 = 0.5f * w0[16];
        w16_1 = 0.5f * w1[16];
        w16_2 = w2[16];
        w16_3 = 0.5f * w3[16];
    }
    const u64 b_if = pk2(0.5f * (bih[j] + bhh[j]),
                         0.5f * (bih[Hsz + j] + bhh[Hsz + j]));
    const u64 b_go = pk2(bih[2 * Hsz + j] + bhh[2 * Hsz + j],
                         0.5f * (bih[3 * Hsz + j] + bhh[3 * Hsz + j]));

    const long OUT_ELEMS = (long)Bsz * Lsz * Hsz;
    const long H_OFF = OUT_ELEMS;
    const long C_OFF = OUT_ELEMS + (long)Bsz * Hsz;
    const long X_OFF = OUT_ELEMS + 2L * (long)Bsz * Hsz;

    const float4* xr0 = (const float4*)(x + (long)bb0 * ROW_STRIDE);
    const float4* xr1 = (const float4*)(x + (long)bb1 * ROW_STRIDE);
    float4* xo0 = (float4*)(out + X_OFF + (long)bb0 * ROW_STRIDE);
    float4* xo1 = (float4*)(out + X_OFF + (long)bb1 * ROW_STRIDE);
    float* ob0 = out + (long)bb0 * OROW_STRIDE;
    float* ob1 = out + (long)bb1 * OROW_STRIDE;

    shp[0][y][j] = 0.0f;          shp[1][y][j] = 0.0f;
    shp[0][y + PAIR_B][j] = 0.0f; shp[1][y + PAIR_B][j] = 0.0f;
    float c0 = 0.0f, hn0 = 0.0f, c1 = 0.0f, hn1 = 0.0f;

    // prefetch first x chunks (17 float4 per row-chunk; thread takes slot j)
    float4 v0 = xr0[j];
    float4 v1 = xr1[j];

    for (int ch = 0; ch < NCHUNK; ch++) {
        const int t0 = ch * Tch;

        // ---- stage both rows' chunks + mirror to x passthrough ----
        if (act0) xo0[ch * Msz + j] = v0;
        if (act1) xo1[ch * Msz + j] = v1;
        {
            float f0[4] = {v0.x, v0.y, v0.z, v0.w};
            float f1[4] = {v1.x, v1.y, v1.z, v1.w};
#pragma unroll
            for (int i = 0; i < 4; i++) {
                int fi = 4 * j + i;                 // chunk float index = t*17 + k
                int t = fi / Msz, k = fi - Msz * t;
                sx[y][k * Tch + t] = f0[i];
                sx[y + PAIR_B][k * Tch + t] = f1[i];
            }
        }
        if (ch + 1 < NCHUNK) {
            v0 = xr0[(ch + 1) * Msz + j];
            v1 = xr1[(ch + 1) * Msz + j];
        }
        __syncthreads();

        // ---- 4-step x-projection burst for BOTH rows (weights LDS shared) ----
        u64 ai0[Tch], ag0[Tch], ai1[Tch], ag1[Tch];
#pragma unroll
        for (int t = 0; t < Tch; t++) {
            ai0[t] = b_if; ag0[t] = b_go;
            ai1[t] = b_if; ag1[t] = b_go;
        }
#pragma unroll
        for (int k = 0; k < Msz; k++) {
            const ulonglong2 w2 = wih_s[k * Hsz + j];
            const float4 xa = *(const float4*)&sx[y][k * Tch];
            const float4 xb = *(const float4*)&sx[y + PAIR_B][k * Tch];
            {
                const u64 d0 = pk2(xa.x, xa.x);
                const u64 d1 = pk2(xa.y, xa.y);
                const u64 d2 = pk2(xa.z, xa.z);
                const u64 d3 = pk2(xa.w, xa.w);
                ffma2(ai0[0], w2.x, d0); ffma2(ag0[0], w2.y, d0);
                ffma2(ai0[1], w2.x, d1); ffma2(ag0[1], w2.y, d1);
                ffma2(ai0[2], w2.x, d2); ffma2(ag0[2], w2.y, d2);
                ffma2(ai0[3], w2.x, d3); ffma2(ag0[3], w2.y, d3);
            }
            {
                const u64 d0 = pk2(xb.x, xb.x);
                const u64 d1 = pk2(xb.y, xb.y);
                const u64 d2 = pk2(xb.z, xb.z);
                const u64 d3 = pk2(xb.w, xb.w);
                ffma2(ai1[0], w2.x, d0); ffma2(ag1[0], w2.y, d0);
                ffma2(ai1[1], w2.x, d1); ffma2(ag1[1], w2.y, d1);
                ffma2(ai1[2], w2.x, d2); ffma2(ag1[2], w2.y, d2);
                ffma2(ai1[3], w2.x, d3); ffma2(ag1[3], w2.y, d3);
            }
        }

        // ---- 4 recurrence steps, two rows per step ----
#pragma unroll
        for (int tl = 0; tl < Tch; tl++) {
            const int t = t0 + tl;
            const int cur = t & 1, nxt = cur ^ 1;

            // ===== row 0 =====
            float zi0, zf0, zg0, zo0;
            {
                const ulonglong2* hp2 = (const ulonglong2*)shp[cur][y];
                const ulonglong2 q0 = hp2[0];
                const ulonglong2 q1 = hp2[1];
                const ulonglong2 q2 = hp2[2];
                const ulonglong2 q3 = hp2[3];
                const float h16 = shp[cur][y][16];

                u64 hc0 = 0ULL, hc1 = 0ULL, hc2 = 0ULL, hc3 = 0ULL;
                ffma2(hc0, wh0[0], q0.x); ffma2(hc1, wh1[0], q0.x);
                ffma2(hc2, wh2[0], q0.x); ffma2(hc3, wh3[0], q0.x);
                ffma2(hc0, wh0[1], q0.y); ffma2(hc1, wh1[1], q0.y);
                ffma2(hc2, wh2[1], q0.y); ffma2(hc3, wh3[1], q0.y);
                ffma2(hc0, wh0[2], q1.x); ffma2(hc1, wh1[2], q1.x);
                ffma2(hc2, wh2[2], q1.x); ffma2(hc3, wh3[2], q1.x);
                ffma2(hc0, wh0[3], q1.y); ffma2(hc1, wh1[3], q1.y);
                ffma2(hc2, wh2[3], q1.y); ffma2(hc3, wh3[3], q1.y);
                ffma2(hc0, wh0[4], q2.x); ffma2(hc1, wh1[4], q2.x);
                ffma2(hc2, wh2[4], q2.x); ffma2(hc3, wh3[4], q2.x);
                ffma2(hc0, wh0[5], q2.y); ffma2(hc1, wh1[5], q2.y);
                ffma2(hc2, wh2[5], q2.y); ffma2(hc3, wh3[5], q2.y);
                ffma2(hc0, wh0[6], q3.x); ffma2(hc1, wh1[6], q3.x);
                ffma2(hc2, wh2[6], q3.x); ffma2(hc3, wh3[6], q3.x);
                ffma2(hc0, wh0[7], q3.y); ffma2(hc1, wh1[7], q3.y);
                ffma2(hc2, wh2[7], q3.y); ffma2(hc3, wh3[7], q3.y);

                float xi, xf_, xg, xo_;
                upk2(ai0[tl], xi, xf_);
                upk2(ag0[tl], xg, xo_);
                float l, h;
                upk2(hc0, l, h); zi0 = fmaf(w16_0, h16, xi  + (l + h));
                upk2(hc1, l, h); zf0 = fmaf(w16_1, h16, xf_ + (l + h));
                upk2(hc2, l, h); zg0 = fmaf(w16_2, h16, xg  + (l + h));
                upk2(hc3, l, h); zo0 = fmaf(w16_3, h16, xo_ + (l + h));
            }

            // ===== row 1 (hc regs reused; row0 activations overlap this) =====
            float zi1, zf1, zg1, zo1;
            {
                const ulonglong2* hp2 = (const ulonglong2*)shp[cur][y + PAIR_B];
                const ulonglong2 q0 = hp2[0];
                const ulonglong2 q1 = hp2[1];
                const ulonglong2 q2 = hp2[2];
                const ulonglong2 q3 = hp2[3];
                const float h16 = shp[cur][y + PAIR_B][16];

                u64 hc0 = 0ULL, hc1 = 0ULL, hc2 = 0ULL, hc3 = 0ULL;
                ffma2(hc0, wh0[0], q0.x); ffma2(hc1, wh1[0], q0.x);
                ffma2(hc2, wh2[0], q0.x); ffma2(hc3, wh3[0], q0.x);
                ffma2(hc0, wh0[1], q0.y); ffma2(hc1, wh1[1], q0.y);
                ffma2(hc2, wh2[1], q0.y); ffma2(hc3, wh3[1], q0.y);
                ffma2(hc0, wh0[2], q1.x); ffma2(hc1, wh1[2], q1.x);
                ffma2(hc2, wh2[2], q1.x); ffma2(hc3, wh3[2], q1.x);
                ffma2(hc0, wh0[3], q1.y); ffma2(hc1, wh1[3], q1.y);
                ffma2(hc2, wh2[3], q1.y); ffma2(hc3, wh3[3], q1.y);
                ffma2(hc0, wh0[4], q2.x); ffma2(hc1, wh1[4], q2.x);
                ffma2(hc2, wh2[4], q2.x); ffma2(hc3, wh3[4], q2.x);
                ffma2(hc0, wh0[5], q2.y); ffma2(hc1, wh1[5], q2.y);
                ffma2(hc2, wh2[5], q2.y); ffma2(hc3, wh3[5], q2.y);
                ffma2(hc0, wh0[6], q3.x); ffma2(hc1, wh1[6], q3.x);
                ffma2(hc2, wh2[6], q3.x); ffma2(hc3, wh3[6], q3.x);
                ffma2(hc0, wh0[7], q3.y); ffma2(hc1, wh1[7], q3.y);
                ffma2(hc2, wh2[7], q3.y); ffma2(hc3, wh3[7], q3.y);

                float xi, xf_, xg, xo_;
                upk2(ai1[tl], xi, xf_);
                upk2(ag1[tl], xg, xo_);
                float l, h;
                upk2(hc0, l, h); zi1 = fmaf(w16_0, h16, xi  + (l + h));
                upk2(hc1, l, h); zf1 = fmaf(w16_1, h16, xf_ + (l + h));
                upk2(hc2, l, h); zg1 = fmaf(w16_2, h16, xg  + (l + h));
                upk2(hc3, l, h); zo1 = fmaf(w16_3, h16, xo_ + (l + h));
            }

            // ===== activations (two independent chains interleave) =====
            const float ig0 = fmaf(0.5f, tanh_ap(zi0), 0.5f);
            const float fg0 = fmaf(0.5f, tanh_ap(zf0), 0.5f);
            const float gg0 = tanh_ap(zg0);
            const float og0 = fmaf(0.5f, tanh_ap(zo0), 0.5f);
            const float ig1 = fmaf(0.5f, tanh_ap(zi1), 0.5f);
            const float fg1 = fmaf(0.5f, tanh_ap(zf1), 0.5f);
            const float gg1 = tanh_ap(zg1);
            const float og1 = fmaf(0.5f, tanh_ap(zo1), 0.5f);
            c0  = fg0 * c0 + ig0 * gg0;
            c1  = fg1 * c1 + ig1 * gg1;
            hn0 = og0 * tanh_ap(c0);
            hn1 = og1 * tanh_ap(c1);

            if (act0) ob0[t * Hsz + j] = hn0;
            if (act1) ob1[t * Hsz + j] = hn1;
            shp[nxt][y][j] = hn0;
            shp[nxt][y + PAIR_B][j] = hn1;
            __syncthreads();
        }
    }

    if (act0) {
        out[H_OFF + (long)r0 * Hsz + j] = hn0;
        out[C_OFF + (long)r0 * Hsz + j] = c0;
    }
    if (act1) {
        out[H_OFF + (long)r1 * Hsz + j] = hn1;
        out[C_OFF + (long)r1 * Hsz + j] = c1;
    }
}

extern "C" void kernel_launch(void* const* d_in, const int* in_sizes, int n_in,
                              void* d_out, int out_size) {
    const float* x   = (const float*)d_in[0];
    const float* Wih = (const float*)d_in[1];
    const float* Whh = (const float*)d_in[2];
    const float* bih = (const float*)d_in[3];
    const float* bhh = (const float*)d_in[4];
    float* out = (float*)d_out;
    (void)in_sizes; (void)n_in; (void)out_size;

    lstm_fused_kernel<<<NBLOCKS, NTHREADS>>>(x, Wih, Whh, bih, bhh, out);
}

// round 15
// speedup vs baseline: 1.7207x; 1.7207x over previous
#include <cuda_runtime.h>

#define Bsz 4096
#define Lsz 512
#define Msz 17
#define Hsz 17
#define Tch 8
#define NCHUNK (Lsz / Tch)          // 64
#define BLOCK_B 7
#define NTHREADS (BLOCK_B * Hsz)    // 119  -> 4 blocks/SM
#define NBLOCKS ((Bsz + BLOCK_B - 1) / BLOCK_B)  // 586
#define CHUNK_F4 (2 * Msz)          // 34 float4 per row-chunk (136 floats)

typedef unsigned long long u64;

__device__ __forceinline__ u64 pk2(float a, float b) {
    u64 r; asm("mov.b64 %0, {%1, %2};" : "=l"(r) : "f"(a), "f"(b)); return r;
}
__device__ __forceinline__ void upk2(u64 v, float &a, float &b) {
    asm("mov.b64 {%0, %1}, %2;" : "=f"(a), "=f"(b) : "l"(v));
}
__device__ __forceinline__ void ffma2(u64 &d, u64 a, u64 b) {
    asm("fma.rn.f32x2 %0, %1, %2, %0;" : "+l"(d) : "l"(a), "l"(b));
}
// single-MUFU tanh; sigmoids = 0.5 + 0.5*tanh(z/2) with /2 folded into weights
__device__ __forceinline__ float tanh_ap(float z) {
    float r; asm("tanh.approx.f32 %0, %1;" : "=f"(r) : "f"(z)); return r;
}

__global__ __launch_bounds__(NTHREADS, 4) void lstm_fused_kernel(
    const float* __restrict__ x,
    const float* __restrict__ Wih,
    const float* __restrict__ Whh,
    const float* __restrict__ bih,
    const float* __restrict__ bhh,
    float* __restrict__ out)
{
    // W_ih: (if-pair, go-pair) side by side -> one LDS.128 per k per chunk
    __shared__ __align__(16) ulonglong2 wih_s[Msz * Hsz];
    // x chunk, PLAIN floats, layout [k][t]: sx[y][k*8+t]; 136 floats/row
    __shared__ __align__(16) float sx[BLOCK_B][Tch * Msz];
    __shared__ __align__(16) float shp[2][BLOCK_B][20];    // h state, plain, dbl-buffered

    const int tid = threadIdx.x;
    const int j = tid % Hsz;
    const int y = tid / Hsz;
    const int b = blockIdx.x * BLOCK_B + y;
    const bool act = (b < Bsz);
    const int bb = act ? b : (Bsz - 1);

    // ---- W_ih into smem; sigmoid gates (i,f,o) pre-scaled by 0.5 ----
    for (int idx = tid; idx < Msz * Hsz; idx += NTHREADS) {
        int k = idx / Hsz, jj = idx % Hsz;
        ulonglong2 w2;
        w2.x = pk2(0.5f * Wih[jj * Msz + k],
                   0.5f * Wih[(Hsz + jj) * Msz + k]);
        w2.y = pk2(Wih[(2 * Hsz + jj) * Msz + k],
                   0.5f * Wih[(3 * Hsz + jj) * Msz + k]);
        wih_s[idx] = w2;
    }

    // ---- W_hh in registers: 8 natural pairs per gate + scalar k=16 column ----
    u64 wh0[8], wh1[8], wh2[8], wh3[8];
    float w16_0, w16_1, w16_2, w16_3;
    {
        const float* w0 = Whh + (0 * Hsz + j) * Hsz;
        const float* w1 = Whh + (1 * Hsz + j) * Hsz;
        const float* w2 = Whh + (2 * Hsz + j) * Hsz;
        const float* w3 = Whh + (3 * Hsz + j) * Hsz;
#pragma unroll
        for (int p = 0; p < 8; p++) {
            wh0[p] = pk2(0.5f * w0[2 * p], 0.5f * w0[2 * p + 1]);
            wh1[p] = pk2(0.5f * w1[2 * p], 0.5f * w1[2 * p + 1]);
            wh2[p] = pk2(w2[2 * p],        w2[2 * p + 1]);
            wh3[p] = pk2(0.5f * w3[2 * p], 0.5f * w3[2 * p + 1]);
        }
        w16_0 = 0.5f * w0[16];
        w16_1 = 0.5f * w1[16];
        w16_2 = w2[16];
        w16_3 = 0.5f * w3[16];
    }
    const u64 b_if = pk2(0.5f * (bih[j] + bhh[j]),
                         0.5f * (bih[Hsz + j] + bhh[Hsz + j]));
    const u64 b_go = pk2(bih[2 * Hsz + j] + bhh[2 * Hsz + j],
                         0.5f * (bih[3 * Hsz + j] + bhh[3 * Hsz + j]));

    const long OUT_ELEMS = (long)Bsz * Lsz * Hsz;
    const long H_OFF = OUT_ELEMS;
    const long C_OFF = OUT_ELEMS + (long)Bsz * Hsz;
    const long X_OFF = OUT_ELEMS + 2L * (long)Bsz * Hsz;

    const float4* xrow4 = (const float4*)(x + (long)bb * Lsz * Msz);
    float4*       xo4   = (float4*)(out + X_OFF + (long)bb * Lsz * Msz);
    float*        obase = out + (long)bb * Lsz * Hsz;

    shp[0][y][j] = 0.0f;
    shp[1][y][j] = 0.0f;
    float c = 0.0f, hn = 0.0f;

    // prefetch first x chunk: 2 float4 per thread (34 f4 per row-chunk)
    float4 v0 = xrow4[j];
    float4 v1 = xrow4[Msz + j];

    for (int ch = 0; ch < NCHUNK; ch++) {
        const int t0 = ch * Tch;

        // ---- stage chunk (v0,v1) + mirror to x passthrough ----
        if (act) {
            xo4[ch * CHUNK_F4 + j] = v0;
            xo4[ch * CHUNK_F4 + Msz + j] = v1;
        }
        {
            float f[8] = {v0.x, v0.y, v0.z, v0.w, v1.x, v1.y, v1.z, v1.w};
#pragma unroll
            for (int i = 0; i < 4; i++) {
                int fi = 4 * j + i;                 // chunk float index = t*17 + k
                int t = fi / Msz, k = fi - Msz * t;
                sx[y][k * Tch + t] = f[i];
            }
#pragma unroll
            for (int i = 0; i < 4; i++) {
                int fi = 68 + 4 * j + i;
                int t = fi / Msz, k = fi - Msz * t;
                sx[y][k * Tch + t] = f[4 + i];
            }
        }
        if (ch + 1 < NCHUNK) {
            v0 = xrow4[(ch + 1) * CHUNK_F4 + j];
            v1 = xrow4[(ch + 1) * CHUNK_F4 + Msz + j];
        }
        __syncthreads();

        // ---- 8-step x-projection burst: per k, 1 LDS.128 w + 2 LDS.128 x ----
        u64 a_if[Tch], a_go[Tch];
#pragma unroll
        for (int t = 0; t < Tch; t++) { a_if[t] = b_if; a_go[t] = b_go; }
#pragma unroll
        for (int k = 0; k < Msz; k++) {
            const ulonglong2 w2 = wih_s[k * Hsz + j];            // {if, go} pairs
            const float4 xa = *(const float4*)&sx[y][k * Tch];     // t0..t3
            const float4 xb = *(const float4*)&sx[y][k * Tch + 4]; // t4..t7
            const u64 d0 = pk2(xa.x, xa.x);
            const u64 d1 = pk2(xa.y, xa.y);
            const u64 d2 = pk2(xa.z, xa.z);
            const u64 d3 = pk2(xa.w, xa.w);
            const u64 d4 = pk2(xb.x, xb.x);
            const u64 d5 = pk2(xb.y, xb.y);
            const u64 d6 = pk2(xb.z, xb.z);
            const u64 d7 = pk2(xb.w, xb.w);
            ffma2(a_if[0], w2.x, d0); ffma2(a_go[0], w2.y, d0);
            ffma2(a_if[1], w2.x, d1); ffma2(a_go[1], w2.y, d1);
            ffma2(a_if[2], w2.x, d2); ffma2(a_go[2], w2.y, d2);
            ffma2(a_if[3], w2.x, d3); ffma2(a_go[3], w2.y, d3);
            ffma2(a_if[4], w2.x, d4); ffma2(a_go[4], w2.y, d4);
            ffma2(a_if[5], w2.x, d5); ffma2(a_go[5], w2.y, d5);
            ffma2(a_if[6], w2.x, d6); ffma2(a_go[6], w2.y, d6);
            ffma2(a_if[7], w2.x, d7); ffma2(a_go[7], w2.y, d7);
        }

        // ---- 8 recurrence steps: h via 4xLDS.128 + 1xLDS.32 ----
#pragma unroll
        for (int tl = 0; tl < Tch; tl++) {
            const int t = t0 + tl;
            const int cur = t & 1, nxt = cur ^ 1;

            const ulonglong2* hp2 = (const ulonglong2*)shp[cur][y];
            const ulonglong2 q0 = hp2[0];
            const ulonglong2 q1 = hp2[1];
            const ulonglong2 q2 = hp2[2];
            const ulonglong2 q3 = hp2[3];
            const float h16 = shp[cur][y][16];

            u64 hc0 = 0ULL, hc1 = 0ULL, hc2 = 0ULL, hc3 = 0ULL;
            ffma2(hc0, wh0[0], q0.x); ffma2(hc1, wh1[0], q0.x);
            ffma2(hc2, wh2[0], q0.x); ffma2(hc3, wh3[0], q0.x);
            ffma2(hc0, wh0[1], q0.y); ffma2(hc1, wh1[1], q0.y);
            ffma2(hc2, wh2[1], q0.y); ffma2(hc3, wh3[1], q0.y);
            ffma2(hc0, wh0[2], q1.x); ffma2(hc1, wh1[2], q1.x);
            ffma2(hc2, wh2[2], q1.x); ffma2(hc3, wh3[2], q1.x);
            ffma2(hc0, wh0[3], q1.y); ffma2(hc1, wh1[3], q1.y);
            ffma2(hc2, wh2[3], q1.y); ffma2(hc3, wh3[3], q1.y);
            ffma2(hc0, wh0[4], q2.x); ffma2(hc1, wh1[4], q2.x);
            ffma2(hc2, wh2[4], q2.x); ffma2(hc3, wh3[4], q2.x);
            ffma2(hc0, wh0[5], q2.y); ffma2(hc1, wh1[5], q2.y);
            ffma2(hc2, wh2[5], q2.y); ffma2(hc3, wh3[5], q2.y);
            ffma2(hc0, wh0[6], q3.x); ffma2(hc1, wh1[6], q3.x);
            ffma2(hc2, wh2[6], q3.x); ffma2(hc3, wh3[6], q3.x);
            ffma2(hc0, wh0[7], q3.y); ffma2(hc1, wh1[7], q3.y);
            ffma2(hc2, wh2[7], q3.y); ffma2(hc3, wh3[7], q3.y);

            float xi, xf_, xg, xo_;
            upk2(a_if[tl], xi, xf_);
            upk2(a_go[tl], xg, xo_);
            float l, h;
            upk2(hc0, l, h); const float zi = fmaf(w16_0, h16, xi  + (l + h));
            upk2(hc1, l, h); const float zf = fmaf(w16_1, h16, xf_ + (l + h));
            upk2(hc2, l, h); const float zg = fmaf(w16_2, h16, xg  + (l + h));
            upk2(hc3, l, h); const float zo = fmaf(w16_3, h16, xo_ + (l + h));

            const float ig = fmaf(0.5f, tanh_ap(zi), 0.5f);
            const float fg = fmaf(0.5f, tanh_ap(zf), 0.5f);
            const float gg = tanh_ap(zg);
            const float og = fmaf(0.5f, tanh_ap(zo), 0.5f);
            c  = fg * c + ig * gg;
            hn = og * tanh_ap(c);

            if (act) obase[t * Hsz + j] = hn;   // direct STG.32 (fire-and-forget)
            shp[nxt][y][j] = hn;
            __syncthreads();
        }
    }

    if (act) {
        out[H_OFF + (long)b * Hsz + j] = hn;
        out[C_OFF + (long)b * Hsz + j] = c;
    }
}

extern "C" void kernel_launch(void* const* d_in, const int* in_sizes, int n_in,
                              void* d_out, int out_size) {
    const float* x   = (const float*)d_in[0];
    const float* Wih = (const float*)d_in[1];
    const float* Whh = (const float*)d_in[2];
    const float* bih = (const float*)d_in[3];
    const float* bhh = (const float*)d_in[4];
    float* out = (float*)d_out;
    (void)in_sizes; (void)n_in; (void)out_size;

    lstm_fused_kernel<<<NBLOCKS, NTHREADS>>>(x, Wih, Whh, bih, bhh, out);
}